// round 8
// baseline (speedup 1.0000x reference)
#include <cuda_runtime.h>

// Problem constants
#define BB 2
#define BN 4096
#define PARTS 16
#define CPART (BN / PARTS)       // 256 columns per partition
#define NPAIR (CPART / 2)        // 128 column pairs
#define TPB 256                  // threads per block
#define RROWS 2                  // rows per thread
#define RPB (TPB * RROWS)        // 512 rows per block
#define ROWTILES (BN / RPB)      // 8
#define LOG2E 1.4426950408889634f
#define LN2 0.6931471805599453f

// Scratch (allocation-free)
__device__ float g_x2[BB * BN];
__device__ float g_y2[BB * BN];
__device__ float g_ax[BB * BN];
__device__ float g_by[BB * BN];
__device__ float g_bx[BB * BN];
__device__ float g_ay[BB * BN];
__device__ float g_pm[4 * BB * PARTS * BN];
__device__ float g_ps[4 * BB * PARTS * BN];

typedef unsigned long long ull;

__device__ __forceinline__ float ex2f(float x) {
    float r;
    asm("ex2.approx.f32 %0, %1;" : "=f"(r) : "f"(x));
    return r;
}
__device__ __forceinline__ float lg2f(float x) {
    float r;
    asm("lg2.approx.f32 %0, %1;" : "=f"(r) : "f"(x));
    return r;
}
__device__ __forceinline__ ull fma2(ull a, ull b, ull c) {
    ull d;
    asm("fma.rn.f32x2 %0, %1, %2, %3;" : "=l"(d) : "l"(a), "l"(b), "l"(c));
    return d;
}
__device__ __forceinline__ ull add2(ull a, ull b) {
    ull d;
    asm("add.rn.f32x2 %0, %1, %2;" : "=l"(d) : "l"(a), "l"(b));
    return d;
}
__device__ __forceinline__ ull fpack(float lo, float hi) {
    ull r;
    asm("mov.b64 %0, {%1, %2};" : "=l"(r) : "f"(lo), "f"(hi));
    return r;
}
__device__ __forceinline__ float flo(ull v) {
    float lo, hi;
    asm("mov.b64 {%0, %1}, %2;" : "=f"(lo), "=f"(hi) : "l"(v));
    return lo;
}
__device__ __forceinline__ float fhi(ull v) {
    float lo, hi;
    asm("mov.b64 {%0, %1}, %2;" : "=f"(lo), "=f"(hi) : "l"(v));
    return hi;
}

// Precompute 0.5*||p||^2 for both point sets
__global__ void sqnorm_kernel(const float* __restrict__ X, const float* __restrict__ Y) {
    int i = blockIdx.x * blockDim.x + threadIdx.x;
    if (i < BB * BN) {
        float a = X[3 * i], b = X[3 * i + 1], c = X[3 * i + 2];
        g_x2[i] = 0.5f * (a * a + b * b + c * c);
        a = Y[3 * i]; b = Y[3 * i + 1]; c = Y[3 * i + 2];
        g_y2[i] = 0.5f * (a * a + b * b + c * c);
    }
}

// One stage: 4 softmins, two-phase per column-partition.
// Log2 domain: v_ij = g_j + (x_i*log2e/eps).y_j, g_j = -12 + (dual_j - 0.5|y_j|^2)*log2e/eps
// Phase 1: exact partition max per row (FMA+FMNMX only).
// Phase 2: s = sum 2^(v - M) with known M (pure stream, no rescales).
// Column-PAIR packing: smem holds (y_j,y_{j+1}) packed; each LDS.128 serves both rows.
// Tasks: t0: C_xx h=a_x | t1: C_yy h=b_y | t2: C_xy h=a_y -> b_x | t3: C_yx h=b_x -> a_y
__global__ __launch_bounds__(TPB) void softmin_kernel(const float* __restrict__ X,
                                                      const float* __restrict__ Y,
                                                      float eps, float dualScale) {
    __shared__ ulonglong2 shA[NPAIR];   // (y0_j,y0_j1),(y1_j,y1_j1)
    __shared__ ulonglong2 shB[NPAIR];   // (y2_j,y2_j1),(g_j , g_j1)

    int bi = blockIdx.x;
    int part    = bi & (PARTS - 1);
    int rowTile = (bi >> 4) & (ROWTILES - 1);
    int b       = (bi >> 7) & (BB - 1);
    int task    = bi >> 8;

    const float* rowP = (task == 0 || task == 2) ? X : Y;
    const float* colP = (task == 0 || task == 3) ? X : Y;
    const float* colQ = (task == 0 || task == 3) ? g_x2 : g_y2;
    const float* colD = (task == 0) ? g_ax : (task == 1) ? g_by : (task == 2) ? g_ay : g_bx;

    const float sLe = LOG2E / eps;
    int tid = threadIdx.x;

    if (tid < NPAIR) {
        int j0  = part * CPART + 2 * tid;
        int ga_ = b * BN + j0;
        int gb_ = ga_ + 1;
        float a0 = colP[3 * ga_], a1 = colP[3 * ga_ + 1], a2 = colP[3 * ga_ + 2];
        float b0 = colP[3 * gb_], b1 = colP[3 * gb_ + 1], b2 = colP[3 * gb_ + 2];
        float gA = -12.0f + (colD[ga_] * dualScale - colQ[ga_]) * sLe;
        float gB = -12.0f + (colD[gb_] * dualScale - colQ[gb_]) * sLe;
        ulonglong2 A, B;
        A.x = fpack(a0, b0); A.y = fpack(a1, b1);
        B.x = fpack(a2, b2); B.y = fpack(gA, gB);
        shA[tid] = A;
        shB[tid] = B;
    }
    __syncthreads();

    int r0 = rowTile * RPB + tid;        // row 0 of this thread
    int r1 = r0 + TPB;                   // row 1
    int g0 = b * BN + r0;
    int g1 = b * BN + r1;
    float xa0 = rowP[3 * g0] * sLe, xa1 = rowP[3 * g0 + 1] * sLe, xa2 = rowP[3 * g0 + 2] * sLe;
    float xb0 = rowP[3 * g1] * sLe, xb1 = rowP[3 * g1 + 1] * sLe, xb2 = rowP[3 * g1 + 2] * sLe;
    ull Xa0 = fpack(xa0, xa0), Xa1 = fpack(xa1, xa1), Xa2 = fpack(xa2, xa2);
    ull Xb0 = fpack(xb0, xb0), Xb1 = fpack(xb1, xb1), Xb2 = fpack(xb2, xb2);

    // ---------- Phase 1: exact max per row over this partition ----------
    float m0a = -3.0e38f, m0b = -3.0e38f, m1a = -3.0e38f, m1b = -3.0e38f;
    for (int p = 0; p < NPAIR; p += 4) {
#pragma unroll
        for (int k = 0; k < 4; k += 2) {
            ulonglong2 A0 = shA[p + k],     B0 = shB[p + k];
            ulonglong2 A1 = shA[p + k + 1], B1 = shB[p + k + 1];
            ull va0 = fma2(Xa0, A0.x, fma2(Xa1, A0.y, fma2(Xa2, B0.x, B0.y)));
            ull vb0 = fma2(Xb0, A0.x, fma2(Xb1, A0.y, fma2(Xb2, B0.x, B0.y)));
            ull va1 = fma2(Xa0, A1.x, fma2(Xa1, A1.y, fma2(Xa2, B1.x, B1.y)));
            ull vb1 = fma2(Xb0, A1.x, fma2(Xb1, A1.y, fma2(Xb2, B1.x, B1.y)));
            m0a = fmaxf(m0a, fmaxf(flo(va0), fhi(va0)));
            m1a = fmaxf(m1a, fmaxf(flo(vb0), fhi(vb0)));
            m0b = fmaxf(m0b, fmaxf(flo(va1), fhi(va1)));
            m1b = fmaxf(m1b, fmaxf(flo(vb1), fhi(vb1)));
        }
    }
    float m0 = fmaxf(m0a, m0b);
    float m1 = fmaxf(m1a, m1b);

    // ---------- Phase 2: sum of 2^(v - M), pure stream ----------
    ull nm0 = fpack(-m0, -m0);
    ull nm1 = fpack(-m1, -m1);
    float s0a = 0.f, s0b = 0.f, s1a = 0.f, s1b = 0.f;
    for (int p = 0; p < NPAIR; p += 4) {
#pragma unroll
        for (int k = 0; k < 4; k += 2) {
            ulonglong2 A0 = shA[p + k],     B0 = shB[p + k];
            ulonglong2 A1 = shA[p + k + 1], B1 = shB[p + k + 1];
            ull va0 = fma2(Xa0, A0.x, fma2(Xa1, A0.y, fma2(Xa2, B0.x, B0.y)));
            ull vb0 = fma2(Xb0, A0.x, fma2(Xb1, A0.y, fma2(Xb2, B0.x, B0.y)));
            ull va1 = fma2(Xa0, A1.x, fma2(Xa1, A1.y, fma2(Xa2, B1.x, B1.y)));
            ull vb1 = fma2(Xb0, A1.x, fma2(Xb1, A1.y, fma2(Xb2, B1.x, B1.y)));
            ull e0 = add2(va0, nm0);
            ull f0 = add2(vb0, nm1);
            ull e1 = add2(va1, nm0);
            ull f1 = add2(vb1, nm1);
            s0a += ex2f(flo(e0)); s0b += ex2f(fhi(e0));
            s1a += ex2f(flo(f0)); s1b += ex2f(fhi(f0));
            s0a += ex2f(flo(e1)); s0b += ex2f(fhi(e1));
            s1a += ex2f(flo(f1)); s1b += ex2f(fhi(f1));
        }
    }

    int base = ((task * BB + b) * PARTS + part) * BN;
    g_pm[base + r0] = m0;
    g_ps[base + r0] = s0a + s0b;
    g_pm[base + r1] = m1;
    g_ps[base + r1] = s1a + s1b;
}

// Combine partition partials -> softmin value; optionally average with old dual (in place).
__global__ void merge_kernel(float eps, int avg) {
    int idx = blockIdx.x * blockDim.x + threadIdx.x;
    if (idx >= 4 * BB * BN) return;
    int task = idx / (BB * BN);
    int rem  = idx - task * (BB * BN);
    int b    = rem / BN;
    int r    = rem - b * BN;

    const float* rowQ = (task == 0 || task == 2) ? g_x2 : g_y2;
    float* outA = (task == 0) ? g_ax : (task == 1) ? g_by : (task == 2) ? g_bx : g_ay;

    int base = (task * BB + b) * (PARTS * BN) + r;
    float M = -3.0e38f;
#pragma unroll
    for (int p = 0; p < PARTS; p++) M = fmaxf(M, g_pm[base + p * BN]);
    float s = 0.f;
#pragma unroll
    for (int p = 0; p < PARTS; p++)
        s = fmaf(g_ps[base + p * BN], ex2f(g_pm[base + p * BN] - M), s);

    float sLe = LOG2E / eps;
    float ri  = -rowQ[rem] * sLe;
    float val = -eps * LN2 * (ri + M + lg2f(s));
    if (avg) val = 0.5f * (outA[rem] + val);
    outA[rem] = val;
}

// F = sum_b [ (1/N) sum_i (b_x - a_x) + (1/M) sum_j (a_y - b_y) ]
__global__ void reduce_kernel(float* __restrict__ out) {
    __shared__ float sh[32];
    int tid = threadIdx.x;
    float acc = 0.f;
    for (int i = tid; i < BB * BN; i += blockDim.x)
        acc += (g_bx[i] - g_ax[i]) + (g_ay[i] - g_by[i]);
    acc *= (1.0f / BN);
#pragma unroll
    for (int o = 16; o; o >>= 1) acc += __shfl_down_sync(0xFFFFFFFFu, acc, o);
    if ((tid & 31) == 0) sh[tid >> 5] = acc;
    __syncthreads();
    if (tid < 32) {
        float v = (tid < (int)(blockDim.x >> 5)) ? sh[tid] : 0.f;
#pragma unroll
        for (int o = 16; o; o >>= 1) v += __shfl_down_sync(0xFFFFFFFFu, v, o);
        if (tid == 0) out[0] = v;
    }
}

extern "C" void kernel_launch(void* const* d_in, const int* in_sizes, int n_in,
                              void* d_out, int out_size) {
    const float* X = (const float*)d_in[0];   // true_data
    const float* Y = (const float*)d_in[1];   // particles
    float* out = (float*)d_out;

    sqnorm_kernel<<<(BB * BN + 255) / 256, 256>>>(X, Y);

    // geomloss eps schedule: [16] + [16,4,1,0.25,0.0625,0.015625,0.00390625] + [0.0025]
    const float epsList[9] = {16.f, 16.f, 4.f, 1.f, 0.25f, 0.0625f,
                              0.015625f, 0.00390625f, 0.0025f};

    const int gridSoft = 4 * BB * ROWTILES * PARTS;   // 1024 blocks
    const int gridMerge = (4 * BB * BN) / 256;        // 128 blocks

    // init (dual term off, assignment)
    softmin_kernel<<<gridSoft, TPB>>>(X, Y, 16.f, 0.f);
    merge_kernel<<<gridMerge, 256>>>(16.f, 0);

    // eps-scaling loop (symmetrized, averaged updates)
    for (int e = 0; e < 9; e++) {
        softmin_kernel<<<gridSoft, TPB>>>(X, Y, epsList[e], 1.f);
        merge_kernel<<<gridMerge, 256>>>(epsList[e], 1);
    }

    // final extrapolation at blur^2 (assignment, no averaging)
    softmin_kernel<<<gridSoft, TPB>>>(X, Y, 0.0025f, 1.f);
    merge_kernel<<<gridMerge, 256>>>(0.0025f, 0);

    reduce_kernel<<<1, 256>>>(out);
}

// round 11
// speedup vs baseline: 1.0618x; 1.0618x over previous
#include <cuda_runtime.h>

// Problem constants
#define BB 2
#define BN 4096
#define PARTS 32
#define CPART (BN / PARTS)       // 128 columns per partition
#define TPB 128                  // threads per block (4 warps)
#define RROWS 2                  // rows per thread (packed f32x2)
#define RPB (TPB * RROWS)        // 256 rows per block
#define ROWTILES (BN / RPB)      // 16
#define LOG2E 1.4426950408889634f
#define LN2 0.6931471805599453f

// Scratch (allocation-free)
__device__ float g_x2[BB * BN];
__device__ float g_y2[BB * BN];
__device__ float g_ax[BB * BN];
__device__ float g_by[BB * BN];
__device__ float g_bx[BB * BN];
__device__ float g_ay[BB * BN];
__device__ float g_pm[4 * BB * PARTS * BN];
__device__ float g_ps[4 * BB * PARTS * BN];

typedef unsigned long long ull;

__device__ __forceinline__ float ex2f(float x) {
    float r;
    asm("ex2.approx.f32 %0, %1;" : "=f"(r) : "f"(x));
    return r;
}
__device__ __forceinline__ float lg2f(float x) {
    float r;
    asm("lg2.approx.f32 %0, %1;" : "=f"(r) : "f"(x));
    return r;
}
__device__ __forceinline__ ull fma2(ull a, ull b, ull c) {
    ull d;
    asm("fma.rn.f32x2 %0, %1, %2, %3;" : "=l"(d) : "l"(a), "l"(b), "l"(c));
    return d;
}
__device__ __forceinline__ ull add2(ull a, ull b) {
    ull d;
    asm("add.rn.f32x2 %0, %1, %2;" : "=l"(d) : "l"(a), "l"(b));
    return d;
}
__device__ __forceinline__ ull fpack(float lo, float hi) {
    ull r;
    asm("mov.b64 %0, {%1, %2};" : "=l"(r) : "f"(lo), "f"(hi));
    return r;
}
__device__ __forceinline__ float flo(ull v) {
    float lo, hi;
    asm("mov.b64 {%0, %1}, %2;" : "=f"(lo), "=f"(hi) : "l"(v));
    return lo;
}
__device__ __forceinline__ float fhi(ull v) {
    float lo, hi;
    asm("mov.b64 {%0, %1}, %2;" : "=f"(lo), "=f"(hi) : "l"(v));
    return hi;
}

// Precompute 0.5*||p||^2 for both point sets
__global__ void sqnorm_kernel(const float* __restrict__ X, const float* __restrict__ Y) {
    int i = blockIdx.x * blockDim.x + threadIdx.x;
    if (i < BB * BN) {
        float a = X[3 * i], b = X[3 * i + 1], c = X[3 * i + 2];
        g_x2[i] = 0.5f * (a * a + b * b + c * c);
        a = Y[3 * i]; b = Y[3 * i + 1]; c = Y[3 * i + 2];
        g_y2[i] = 0.5f * (a * a + b * b + c * c);
    }
}

// One stage: 4 softmins. Log2-domain LSE, chunk-local max + deferred (m,s) combine.
// v_ij = g_j + (x_i*log2e/eps).y_j,  g_j = -12 + (dual_j - 0.5|y_j|^2)*log2e/eps
// Each 8-column chunk computes its own local max + local sum (no dependence on
// running state -> no serial rescale chain); running (m,s) merged with 2 EX2/row.
// Packed f32x2: 2 rows per thread; smem columns duplicated (y,y) for direct packed ops.
// Tasks: t0: C_xx h=a_x | t1: C_yy h=b_y | t2: C_xy h=a_y -> b_x | t3: C_yx h=b_x -> a_y
__global__ __launch_bounds__(TPB) void softmin_kernel(const float* __restrict__ X,
                                                      const float* __restrict__ Y,
                                                      float eps, float dualScale) {
    __shared__ ulonglong2 shA[CPART];   // (y0,y0),(y1,y1)
    __shared__ ulonglong2 shB[CPART];   // (y2,y2),(g , g)

    int bi = blockIdx.x;
    int part    = bi & (PARTS - 1);
    int rowTile = (bi >> 5) & (ROWTILES - 1);
    int b       = (bi >> 9) & (BB - 1);
    int task    = bi >> 10;

    const float* rowP = (task == 0 || task == 2) ? X : Y;
    const float* colP = (task == 0 || task == 3) ? X : Y;
    const float* colQ = (task == 0 || task == 3) ? g_x2 : g_y2;
    const float* colD = (task == 0) ? g_ax : (task == 1) ? g_by : (task == 2) ? g_ay : g_bx;

    const float sLe = LOG2E / eps;
    int tid = threadIdx.x;

    {   // one column per thread (CPART == TPB)
        int j  = part * CPART + tid;
        int gj = b * BN + j;
        float y0 = colP[3 * gj], y1 = colP[3 * gj + 1], y2 = colP[3 * gj + 2];
        float g  = -12.0f + (colD[gj] * dualScale - colQ[gj]) * sLe;
        ulonglong2 A, B;
        A.x = fpack(y0, y0); A.y = fpack(y1, y1);
        B.x = fpack(y2, y2); B.y = fpack(g, g);
        shA[tid] = A;
        shB[tid] = B;
    }
    __syncthreads();

    int r0 = rowTile * RPB + tid;        // row for lo lane
    int r1 = r0 + TPB;                   // row for hi lane
    int g0 = b * BN + r0;
    int g1 = b * BN + r1;
    ull X0 = fpack(rowP[3 * g0] * sLe,     rowP[3 * g1] * sLe);
    ull X1 = fpack(rowP[3 * g0 + 1] * sLe, rowP[3 * g1 + 1] * sLe);
    ull X2 = fpack(rowP[3 * g0 + 2] * sLe, rowP[3 * g1 + 2] * sLe);

    float m0 = -3.0e38f, m1 = -3.0e38f;
    float s0 = 0.f, s1 = 0.f;

    for (int p = 0; p < CPART; p += 8) {
        ull v[8];
#pragma unroll
        for (int k = 0; k < 8; k++) {
            ulonglong2 A = shA[p + k];
            ulonglong2 B = shB[p + k];
            v[k] = fma2(X0, A.x, fma2(X1, A.y, fma2(X2, B.x, B.y)));
        }
        // chunk-local max per row (independent of running state)
        float c0 = fmaxf(fmaxf(fmaxf(flo(v[0]), flo(v[1])), fmaxf(flo(v[2]), flo(v[3]))),
                         fmaxf(fmaxf(flo(v[4]), flo(v[5])), fmaxf(flo(v[6]), flo(v[7]))));
        float c1 = fmaxf(fmaxf(fmaxf(fhi(v[0]), fhi(v[1])), fmaxf(fhi(v[2]), fhi(v[3]))),
                         fmaxf(fmaxf(fhi(v[4]), fhi(v[5])), fmaxf(fhi(v[6]), fhi(v[7]))));
        ull nc = fpack(-c0, -c1);
        // chunk-local sums (16 independent EX2s)
        float cs00 = 0.f, cs01 = 0.f, cs10 = 0.f, cs11 = 0.f;
#pragma unroll
        for (int k = 0; k < 8; k += 2) {
            ull e0 = add2(v[k], nc);
            ull e1 = add2(v[k + 1], nc);
            cs00 += ex2f(flo(e0)); cs10 += ex2f(fhi(e0));
            cs01 += ex2f(flo(e1)); cs11 += ex2f(fhi(e1));
        }
        // deferred combine into running (m,s): short lat-4 chain + 4 EX2 off critical path
        float mn0 = fmaxf(m0, c0);
        float mn1 = fmaxf(m1, c1);
        s0 = fmaf(s0, ex2f(m0 - mn0), (cs00 + cs01) * ex2f(c0 - mn0));
        s1 = fmaf(s1, ex2f(m1 - mn1), (cs10 + cs11) * ex2f(c1 - mn1));
        m0 = mn0;
        m1 = mn1;
    }

    int base = ((task * BB + b) * PARTS + part) * BN;
    g_pm[base + r0] = m0;
    g_ps[base + r0] = s0;
    g_pm[base + r1] = m1;
    g_ps[base + r1] = s1;
}

// Combine partition partials -> softmin value; optionally average with old dual (in place).
__global__ void merge_kernel(float eps, int avg) {
    int idx = blockIdx.x * blockDim.x + threadIdx.x;
    if (idx >= 4 * BB * BN) return;
    int task = idx / (BB * BN);
    int rem  = idx - task * (BB * BN);
    int b    = rem / BN;
    int r    = rem - b * BN;

    const float* rowQ = (task == 0 || task == 2) ? g_x2 : g_y2;
    float* outA = (task == 0) ? g_ax : (task == 1) ? g_by : (task == 2) ? g_bx : g_ay;

    int base = (task * BB + b) * (PARTS * BN) + r;
    float M = -3.0e38f;
#pragma unroll
    for (int p = 0; p < PARTS; p++) M = fmaxf(M, g_pm[base + p * BN]);
    float s = 0.f;
#pragma unroll
    for (int p = 0; p < PARTS; p++)
        s = fmaf(g_ps[base + p * BN], ex2f(g_pm[base + p * BN] - M), s);

    float sLe = LOG2E / eps;
    float ri  = -rowQ[rem] * sLe;
    float val = -eps * LN2 * (ri + M + lg2f(s));
    if (avg) val = 0.5f * (outA[rem] + val);
    outA[rem] = val;
}

// F = sum_b [ (1/N) sum_i (b_x - a_x) + (1/M) sum_j (a_y - b_y) ]
__global__ void reduce_kernel(float* __restrict__ out) {
    __shared__ float sh[32];
    int tid = threadIdx.x;
    float acc = 0.f;
    for (int i = tid; i < BB * BN; i += blockDim.x)
        acc += (g_bx[i] - g_ax[i]) + (g_ay[i] - g_by[i]);
    acc *= (1.0f / BN);
#pragma unroll
    for (int o = 16; o; o >>= 1) acc += __shfl_down_sync(0xFFFFFFFFu, acc, o);
    if ((tid & 31) == 0) sh[tid >> 5] = acc;
    __syncthreads();
    if (tid < 32) {
        float v = (tid < (int)(blockDim.x >> 5)) ? sh[tid] : 0.f;
#pragma unroll
        for (int o = 16; o; o >>= 1) v += __shfl_down_sync(0xFFFFFFFFu, v, o);
        if (tid == 0) out[0] = v;
    }
}

extern "C" void kernel_launch(void* const* d_in, const int* in_sizes, int n_in,
                              void* d_out, int out_size) {
    const float* X = (const float*)d_in[0];   // true_data
    const float* Y = (const float*)d_in[1];   // particles
    float* out = (float*)d_out;

    sqnorm_kernel<<<(BB * BN + 255) / 256, 256>>>(X, Y);

    // geomloss eps schedule: [16] + [16,4,1,0.25,0.0625,0.015625,0.00390625] + [0.0025]
    const float epsList[9] = {16.f, 16.f, 4.f, 1.f, 0.25f, 0.0625f,
                              0.015625f, 0.00390625f, 0.0025f};

    const int gridSoft = 4 * BB * ROWTILES * PARTS;   // 4096 blocks
    const int gridMerge = (4 * BB * BN) / 256;        // 128 blocks

    // init (dual term off, assignment)
    softmin_kernel<<<gridSoft, TPB>>>(X, Y, 16.f, 0.f);
    merge_kernel<<<gridMerge, 256>>>(16.f, 0);

    // eps-scaling loop (symmetrized, averaged updates)
    for (int e = 0; e < 9; e++) {
        softmin_kernel<<<gridSoft, TPB>>>(X, Y, epsList[e], 1.f);
        merge_kernel<<<gridMerge, 256>>>(epsList[e], 1);
    }

    // final extrapolation at blur^2 (assignment, no averaging)
    softmin_kernel<<<gridSoft, TPB>>>(X, Y, 0.0025f, 1.f);
    merge_kernel<<<gridMerge, 256>>>(0.0025f, 0);

    reduce_kernel<<<1, 256>>>(out);
}

// round 13
// speedup vs baseline: 1.1517x; 1.0847x over previous
#include <cuda_runtime.h>

// Problem constants
#define BB 2
#define BN 4096
#define PARTS 32
#define CPART (BN / PARTS)       // 128 columns per partition
#define TPB 128                  // threads per block (4 warps)
#define RROWS 2                  // rows per thread (scalar, shared LDS)
#define RPB (TPB * RROWS)        // 256 rows per block
#define ROWTILES (BN / RPB)      // 16
#define LOG2E 1.4426950408889634f
#define LN2 0.6931471805599453f

// Scratch (allocation-free)
__device__ float g_x2[BB * BN];
__device__ float g_y2[BB * BN];
__device__ float g_ax[BB * BN];
__device__ float g_by[BB * BN];
__device__ float g_bx[BB * BN];
__device__ float g_ay[BB * BN];
__device__ float g_pm[4 * BB * PARTS * BN];
__device__ float g_ps[4 * BB * PARTS * BN];

__device__ __forceinline__ float ex2f(float x) {
    float r;
    asm("ex2.approx.f32 %0, %1;" : "=f"(r) : "f"(x));
    return r;
}
__device__ __forceinline__ float lg2f(float x) {
    float r;
    asm("lg2.approx.f32 %0, %1;" : "=f"(r) : "f"(x));
    return r;
}

// Precompute 0.5*||p||^2 for both point sets
__global__ void sqnorm_kernel(const float* __restrict__ X, const float* __restrict__ Y) {
    int i = blockIdx.x * blockDim.x + threadIdx.x;
    if (i < BB * BN) {
        float a = X[3 * i], b = X[3 * i + 1], c = X[3 * i + 2];
        g_x2[i] = 0.5f * (a * a + b * b + c * c);
        a = Y[3 * i]; b = Y[3 * i + 1]; c = Y[3 * i + 2];
        g_y2[i] = 0.5f * (a * a + b * b + c * c);
    }
}

// One stage: 4 softmins. Log2-domain online LSE, SCALAR math (no f32x2 packing tax),
// 2 rows per thread sharing each uniform LDS.128 column load.
// v_ij = g_j + (x_i*log2e/eps).y_j,  g_j = -12 + (dual_j - 0.5|y_j|^2)*log2e/eps
// Tasks: t0: C_xx h=a_x | t1: C_yy h=b_y | t2: C_xy h=a_y -> b_x | t3: C_yx h=b_x -> a_y
__global__ __launch_bounds__(TPB) void softmin_kernel(const float* __restrict__ X,
                                                      const float* __restrict__ Y,
                                                      float eps, float dualScale) {
    __shared__ float4 shY[CPART];   // (y0, y1, y2, g)

    int bi = blockIdx.x;
    int part    = bi & (PARTS - 1);
    int rowTile = (bi >> 5) & (ROWTILES - 1);
    int b       = (bi >> 9) & (BB - 1);
    int task    = bi >> 10;

    const float* rowP = (task == 0 || task == 2) ? X : Y;
    const float* colP = (task == 0 || task == 3) ? X : Y;
    const float* colQ = (task == 0 || task == 3) ? g_x2 : g_y2;
    const float* colD = (task == 0) ? g_ax : (task == 1) ? g_by : (task == 2) ? g_ay : g_bx;

    const float sLe = LOG2E / eps;
    int tid = threadIdx.x;

    {   // one column per thread (CPART == TPB)
        int j  = part * CPART + tid;
        int gj = b * BN + j;
        float y0 = colP[3 * gj], y1 = colP[3 * gj + 1], y2 = colP[3 * gj + 2];
        float g  = -12.0f + (colD[gj] * dualScale - colQ[gj]) * sLe;
        shY[tid] = make_float4(y0, y1, y2, g);
    }
    __syncthreads();

    int r0 = rowTile * RPB + tid;        // row 0 of this thread
    int r1 = r0 + TPB;                   // row 1
    int g0 = b * BN + r0;
    int g1 = b * BN + r1;
    float xa0 = rowP[3 * g0] * sLe, xa1 = rowP[3 * g0 + 1] * sLe, xa2 = rowP[3 * g0 + 2] * sLe;
    float xb0 = rowP[3 * g1] * sLe, xb1 = rowP[3 * g1 + 1] * sLe, xb2 = rowP[3 * g1 + 2] * sLe;

    float m0 = -3.0e38f, m1 = -3.0e38f;
    float s0a = 0.f, s0b = 0.f, s1a = 0.f, s1b = 0.f;

    for (int p = 0; p < CPART; p += 8) {
        float va[8], vb[8];
#pragma unroll
        for (int k = 0; k < 8; k++) {
            float4 c = shY[p + k];
            va[k] = fmaf(xa0, c.x, fmaf(xa1, c.y, fmaf(xa2, c.z, c.w)));
            vb[k] = fmaf(xb0, c.x, fmaf(xb1, c.y, fmaf(xb2, c.z, c.w)));
        }
        float ca = fmaxf(fmaxf(fmaxf(va[0], va[1]), fmaxf(va[2], va[3])),
                         fmaxf(fmaxf(va[4], va[5]), fmaxf(va[6], va[7])));
        float cb = fmaxf(fmaxf(fmaxf(vb[0], vb[1]), fmaxf(vb[2], vb[3])),
                         fmaxf(fmaxf(vb[4], vb[5]), fmaxf(vb[6], vb[7])));
        // branchless rescale: sc == 1.0 exactly when max unchanged
        float mna = fmaxf(m0, ca);
        float mnb = fmaxf(m1, cb);
        float sca = ex2f(m0 - mna);
        float scb = ex2f(m1 - mnb);
        s0a *= sca; s0b *= sca; m0 = mna;
        s1a *= scb; s1b *= scb; m1 = mnb;
#pragma unroll
        for (int k = 0; k < 8; k += 2) {
            s0a += ex2f(va[k] - m0);
            s0b += ex2f(va[k + 1] - m0);
            s1a += ex2f(vb[k] - m1);
            s1b += ex2f(vb[k + 1] - m1);
        }
    }

    int base = ((task * BB + b) * PARTS + part) * BN;
    g_pm[base + r0] = m0;
    g_ps[base + r0] = s0a + s0b;
    g_pm[base + r1] = m1;
    g_ps[base + r1] = s1a + s1b;
}

// Combine partition partials -> softmin value; optionally average with old dual (in place).
__global__ void merge_kernel(float eps, int avg) {
    int idx = blockIdx.x * blockDim.x + threadIdx.x;
    if (idx >= 4 * BB * BN) return;
    int task = idx / (BB * BN);
    int rem  = idx - task * (BB * BN);
    int b    = rem / BN;
    int r    = rem - b * BN;

    const float* rowQ = (task == 0 || task == 2) ? g_x2 : g_y2;
    float* outA = (task == 0) ? g_ax : (task == 1) ? g_by : (task == 2) ? g_bx : g_ay;

    int base = (task * BB + b) * (PARTS * BN) + r;
    float M = -3.0e38f;
#pragma unroll
    for (int p = 0; p < PARTS; p++) M = fmaxf(M, g_pm[base + p * BN]);
    float s = 0.f;
#pragma unroll
    for (int p = 0; p < PARTS; p++)
        s = fmaf(g_ps[base + p * BN], ex2f(g_pm[base + p * BN] - M), s);

    float sLe = LOG2E / eps;
    float ri  = -rowQ[rem] * sLe;
    float val = -eps * LN2 * (ri + M + lg2f(s));
    if (avg) val = 0.5f * (outA[rem] + val);
    outA[rem] = val;
}

// F = sum_b [ (1/N) sum_i (b_x - a_x) + (1/M) sum_j (a_y - b_y) ]
__global__ void reduce_kernel(float* __restrict__ out) {
    __shared__ float sh[32];
    int tid = threadIdx.x;
    float acc = 0.f;
    for (int i = tid; i < BB * BN; i += blockDim.x)
        acc += (g_bx[i] - g_ax[i]) + (g_ay[i] - g_by[i]);
    acc *= (1.0f / BN);
#pragma unroll
    for (int o = 16; o; o >>= 1) acc += __shfl_down_sync(0xFFFFFFFFu, acc, o);
    if ((tid & 31) == 0) sh[tid >> 5] = acc;
    __syncthreads();
    if (tid < 32) {
        float v = (tid < (int)(blockDim.x >> 5)) ? sh[tid] : 0.f;
#pragma unroll
        for (int o = 16; o; o >>= 1) v += __shfl_down_sync(0xFFFFFFFFu, v, o);
        if (tid == 0) out[0] = v;
    }
}

extern "C" void kernel_launch(void* const* d_in, const int* in_sizes, int n_in,
                              void* d_out, int out_size) {
    const float* X = (const float*)d_in[0];   // true_data
    const float* Y = (const float*)d_in[1];   // particles
    float* out = (float*)d_out;

    sqnorm_kernel<<<(BB * BN + 255) / 256, 256>>>(X, Y);

    // geomloss eps schedule: [16] + [16,4,1,0.25,0.0625,0.015625,0.00390625] + [0.0025]
    const float epsList[9] = {16.f, 16.f, 4.f, 1.f, 0.25f, 0.0625f,
                              0.015625f, 0.00390625f, 0.0025f};

    const int gridSoft = 4 * BB * ROWTILES * PARTS;   // 4096 blocks
    const int gridMerge = (4 * BB * BN) / 256;        // 128 blocks

    // init (dual term off, assignment)
    softmin_kernel<<<gridSoft, TPB>>>(X, Y, 16.f, 0.f);
    merge_kernel<<<gridMerge, 256>>>(16.f, 0);

    // eps-scaling loop (symmetrized, averaged updates)
    for (int e = 0; e < 9; e++) {
        softmin_kernel<<<gridSoft, TPB>>>(X, Y, epsList[e], 1.f);
        merge_kernel<<<gridMerge, 256>>>(epsList[e], 1);
    }

    // final extrapolation at blur^2 (assignment, no averaging)
    softmin_kernel<<<gridSoft, TPB>>>(X, Y, 0.0025f, 1.f);
    merge_kernel<<<gridMerge, 256>>>(0.0025f, 0);

    reduce_kernel<<<1, 256>>>(out);
}